// round 1
// baseline (speedup 1.0000x reference)
#include <cuda_runtime.h>
#include <math.h>

#define ROWS  (8 * 4096)   // B*S = 32768
#define CH    2048         // C == M

// ---------------- scratch (allocation-free rule: __device__ globals) ----------------
__device__ float g_act[(size_t)ROWS * CH];  // LN+SiLU activations (input to GEMMs)
__device__ float g_h1 [(size_t)ROWS * CH];  // output of first GEMM

// ---------------- block reduction: sum + sumsq ----------------
__inline__ __device__ float2 block_reduce_sum2(float a, float b) {
    __shared__ float sa[8], sb[8];
    int lane = threadIdx.x & 31;
    int w    = threadIdx.x >> 5;
    #pragma unroll
    for (int off = 16; off > 0; off >>= 1) {
        a += __shfl_down_sync(0xffffffffu, a, off);
        b += __shfl_down_sync(0xffffffffu, b, off);
    }
    if (lane == 0) { sa[w] = a; sb[w] = b; }
    __syncthreads();
    if (w == 0) {
        a = (lane < 8) ? sa[lane] : 0.0f;
        b = (lane < 8) ? sb[lane] : 0.0f;
        #pragma unroll
        for (int off = 4; off > 0; off >>= 1) {
            a += __shfl_down_sync(0xffffffffu, a, off);
            b += __shfl_down_sync(0xffffffffu, b, off);
        }
        if (lane == 0) { sa[0] = a; sb[0] = b; }
    }
    __syncthreads();
    return make_float2(sa[0], sb[0]);
}

// ---------------- fused LayerNorm + SiLU, one row (2048 elems) per block ----------------
__global__ void __launch_bounds__(256) ln_silu_kernel(
    const float* __restrict__ x,
    const float* __restrict__ gamma,
    const float* __restrict__ beta,
    float* __restrict__ out)
{
    const size_t row = blockIdx.x;
    const int tid = threadIdx.x;                 // 256 threads, 2 float4 each
    const float4* xr = (const float4*)(x + row * (size_t)CH);

    float4 v0 = xr[tid];
    float4 v1 = xr[tid + 256];

    float s  = v0.x + v0.y + v0.z + v0.w + v1.x + v1.y + v1.z + v1.w;
    float sq = v0.x*v0.x + v0.y*v0.y + v0.z*v0.z + v0.w*v0.w
             + v1.x*v1.x + v1.y*v1.y + v1.z*v1.z + v1.w*v1.w;

    float2 r = block_reduce_sum2(s, sq);
    const float inv_n = 1.0f / (float)CH;
    float mu  = r.x * inv_n;
    float var = r.y * inv_n - mu * mu;
    float inv = rsqrtf(var + 1e-6f);

    const float4* gr = (const float4*)gamma;
    const float4* br = (const float4*)beta;
    float4 g0 = gr[tid],       g1v = gr[tid + 256];
    float4 b0 = br[tid],       b1v = br[tid + 256];

    float4 o0, o1;
    #define LNS(xx, gg, bb, oo) { float y = (xx - mu) * inv * gg + bb; oo = y * (1.0f / (1.0f + __expf(-y))); }
    LNS(v0.x, g0.x,  b0.x,  o0.x); LNS(v0.y, g0.y,  b0.y,  o0.y);
    LNS(v0.z, g0.z,  b0.z,  o0.z); LNS(v0.w, g0.w,  b0.w,  o0.w);
    LNS(v1.x, g1v.x, b1v.x, o1.x); LNS(v1.y, g1v.y, b1v.y, o1.y);
    LNS(v1.z, g1v.z, b1v.z, o1.z); LNS(v1.w, g1v.w, b1v.w, o1.w);
    #undef LNS

    float4* outr = (float4*)(out + row * (size_t)CH);
    outr[tid]       = o0;
    outr[tid + 256] = o1;
}

// ---------------- fp32 SGEMM: C[ROWS x CH] = A[ROWS x CH] @ W[CH x CH] + bias (+resid) ----------------
// 128x128 block tile, BK=8, 256 threads, 8x8 per-thread micro-tile.
template <bool RESID>
__global__ void __launch_bounds__(256) sgemm_kernel(
    const float* __restrict__ A,
    const float* __restrict__ W,
    const float* __restrict__ bias,
    const float* __restrict__ resid,
    float* __restrict__ C)
{
    constexpr int BM = 128, BN = 128, BK = 8;
    __shared__ float As[BK][BM];   // transposed stage
    __shared__ float Bs[BK][BN];

    const int bx = blockIdx.x;     // N tile
    const int by = blockIdx.y;     // M tile
    const int tid = threadIdx.x;
    const int tx = tid & 15;       // 0..15 -> 8 cols each
    const int ty = tid >> 4;       // 0..15 -> 8 rows each

    // A tile load mapping: 128 rows x 8 cols -> 256 float4 (one per thread)
    const int arow = tid >> 1;           // 0..127
    const int acol = (tid & 1) * 4;      // 0 or 4
    // B tile load mapping: 8 rows x 128 cols -> 256 float4
    const int brow = tid >> 5;           // 0..7
    const int bcol = (tid & 31) * 4;     // 0..124

    const float* Aptr = A + ((size_t)(by * BM + arow)) * CH + acol;
    const float* Wptr = W + ((size_t)brow) * CH + (size_t)bx * BN + bcol;

    float acc[8][8];
    #pragma unroll
    for (int i = 0; i < 8; i++)
        #pragma unroll
        for (int j = 0; j < 8; j++) acc[i][j] = 0.0f;

    for (int k0 = 0; k0 < CH; k0 += BK) {
        float4 av = *(const float4*)(Aptr + k0);
        float4 bv = *(const float4*)(Wptr + (size_t)k0 * CH);

        As[acol + 0][arow] = av.x;
        As[acol + 1][arow] = av.y;
        As[acol + 2][arow] = av.z;
        As[acol + 3][arow] = av.w;
        *(float4*)&Bs[brow][bcol] = bv;
        __syncthreads();

        #pragma unroll
        for (int k = 0; k < BK; k++) {
            float a[8], b[8];
            #pragma unroll
            for (int i = 0; i < 8; i++) a[i] = As[k][ty * 8 + i];
            #pragma unroll
            for (int j = 0; j < 8; j++) b[j] = Bs[k][tx * 8 + j];
            #pragma unroll
            for (int i = 0; i < 8; i++)
                #pragma unroll
                for (int j = 0; j < 8; j++)
                    acc[i][j] += a[i] * b[j];
        }
        __syncthreads();
    }

    // epilogue: + bias (+ residual), vectorized stores
    const int ncol0 = bx * BN + tx * 8;
    float bia[8];
    #pragma unroll
    for (int j = 0; j < 8; j++) bia[j] = bias[ncol0 + j];

    #pragma unroll
    for (int i = 0; i < 8; i++) {
        const size_t row = (size_t)(by * BM + ty * 8 + i);
        float* crow = C + row * CH + ncol0;
        if (RESID) {
            const float4* rrow = (const float4*)(resid + row * CH + ncol0);
            float4 r0 = rrow[0], r1 = rrow[1];
            float4 c0, c1;
            c0.x = acc[i][0] + bia[0] + r0.x;  c0.y = acc[i][1] + bia[1] + r0.y;
            c0.z = acc[i][2] + bia[2] + r0.z;  c0.w = acc[i][3] + bia[3] + r0.w;
            c1.x = acc[i][4] + bia[4] + r1.x;  c1.y = acc[i][5] + bia[5] + r1.y;
            c1.z = acc[i][6] + bia[6] + r1.z;  c1.w = acc[i][7] + bia[7] + r1.w;
            ((float4*)crow)[0] = c0;
            ((float4*)crow)[1] = c1;
        } else {
            float4 c0, c1;
            c0.x = acc[i][0] + bia[0];  c0.y = acc[i][1] + bia[1];
            c0.z = acc[i][2] + bia[2];  c0.w = acc[i][3] + bia[3];
            c1.x = acc[i][4] + bia[4];  c1.y = acc[i][5] + bia[5];
            c1.z = acc[i][6] + bia[6];  c1.w = acc[i][7] + bia[7];
            ((float4*)crow)[0] = c0;
            ((float4*)crow)[1] = c1;
        }
    }
}

// ---------------- launch ----------------
extern "C" void kernel_launch(void* const* d_in, const int* in_sizes, int n_in,
                              void* d_out, int out_size)
{
    const float* x   = (const float*)d_in[0];
    const float* w1  = (const float*)d_in[1];
    const float* b1  = (const float*)d_in[2];
    const float* w2  = (const float*)d_in[3];
    const float* b2  = (const float*)d_in[4];
    const float* g1  = (const float*)d_in[5];
    const float* be1 = (const float*)d_in[6];
    const float* g2  = (const float*)d_in[7];
    const float* be2 = (const float*)d_in[8];
    float* out = (float*)d_out;

    float* act; float* h1;
    cudaGetSymbolAddress((void**)&act, g_act);
    cudaGetSymbolAddress((void**)&h1,  g_h1);

    dim3 gemm_grid(CH / 128, ROWS / 128);   // (16, 256)

    ln_silu_kernel<<<ROWS, 256>>>(x, g1, be1, act);
    sgemm_kernel<false><<<gemm_grid, 256>>>(act, w1, b1, nullptr, h1);
    ln_silu_kernel<<<ROWS, 256>>>(h1, g2, be2, act);
    sgemm_kernel<true><<<gemm_grid, 256>>>(act, w2, b2, x, out);
}

// round 3
// speedup vs baseline: 3.1855x; 3.1855x over previous
#include <cuda_runtime.h>
#include <cuda_bf16.h>
#include <stdint.h>
#include <math.h>

#define ROWS   (8 * 4096)     // 32768
#define CH     2048
#define BM     128
#define BN     128
#define BK     64
#define CHUNKS (CH / BK)      // 32

// SMEM: per stage 4 matrices of [128][64] bf16 = 16KB each
#define MAT_BYTES   (128 * 64 * 2)
#define OFF_AHI     0
#define OFF_ALO     (MAT_BYTES)
#define OFF_WHI     (2 * MAT_BYTES)
#define OFF_WLO     (3 * MAT_BYTES)
#define STAGE_BYTES (4 * MAT_BYTES)          // 64KB
#define SMEM_TOTAL  (2 * STAGE_BYTES)        // 128KB

// ---- scratch (__device__ globals; allocation-free rule) ----
__device__ __nv_bfloat16 g_act_hi[(size_t)ROWS * CH];
__device__ __nv_bfloat16 g_act_lo[(size_t)ROWS * CH];
__device__ float         g_h1   [(size_t)ROWS * CH];
__device__ __nv_bfloat16 g_w1_hi[(size_t)CH * CH];
__device__ __nv_bfloat16 g_w1_lo[(size_t)CH * CH];
__device__ __nv_bfloat16 g_w2_hi[(size_t)CH * CH];
__device__ __nv_bfloat16 g_w2_lo[(size_t)CH * CH];

// ======================= PTX helpers =======================
__device__ __forceinline__ uint32_t smem_u32(const void* p) {
    uint32_t a;
    asm("{ .reg .u64 t; cvta.to.shared.u64 t, %1; cvt.u32.u64 %0, t; }" : "=r"(a) : "l"(p));
    return a;
}

__device__ __forceinline__ void cp16(uint32_t s, const void* g) {
    asm volatile("cp.async.cg.shared.global [%0], [%1], 16;" :: "r"(s), "l"(g));
}

#define CP_COMMIT()  asm volatile("cp.async.commit_group;" ::: "memory")
#define CP_WAIT1()   asm volatile("cp.async.wait_group 1;" ::: "memory")
#define CP_WAIT0()   asm volatile("cp.async.wait_group 0;" ::: "memory")

#define LDSM4(r, addr) \
    asm volatile("ldmatrix.sync.aligned.m8n8.x4.shared.b16 {%0,%1,%2,%3}, [%4];" \
        : "=r"((r)[0]), "=r"((r)[1]), "=r"((r)[2]), "=r"((r)[3]) : "r"(addr))

#define MMA16816(c, a, b) \
    asm volatile("mma.sync.aligned.m16n8k16.row.col.f32.bf16.bf16.f32 " \
        "{%0,%1,%2,%3}, {%4,%5,%6,%7}, {%8,%9}, {%0,%1,%2,%3};" \
        : "+f"((c)[0]), "+f"((c)[1]), "+f"((c)[2]), "+f"((c)[3]) \
        : "r"((a)[0]), "r"((a)[1]), "r"((a)[2]), "r"((a)[3]), "r"((b)[0]), "r"((b)[1]))

// swizzled smem byte offset for (row, 16B-chunk kc) in a [128][64]bf16 matrix
__device__ __forceinline__ uint32_t swz(int row, int kc) {
    return (uint32_t)(row * 128 + ((kc ^ (row & 7)) << 4));
}

// ======================= LN + SiLU + bf16 split =======================
__inline__ __device__ float2 block_reduce_sum2(float a, float b) {
    __shared__ float sa[8], sb[8];
    int lane = threadIdx.x & 31, w = threadIdx.x >> 5;
    #pragma unroll
    for (int off = 16; off > 0; off >>= 1) {
        a += __shfl_down_sync(0xffffffffu, a, off);
        b += __shfl_down_sync(0xffffffffu, b, off);
    }
    if (lane == 0) { sa[w] = a; sb[w] = b; }
    __syncthreads();
    if (w == 0) {
        a = (lane < 8) ? sa[lane] : 0.0f;
        b = (lane < 8) ? sb[lane] : 0.0f;
        #pragma unroll
        for (int off = 4; off > 0; off >>= 1) {
            a += __shfl_down_sync(0xffffffffu, a, off);
            b += __shfl_down_sync(0xffffffffu, b, off);
        }
        if (lane == 0) { sa[0] = a; sb[0] = b; }
    }
    __syncthreads();
    return make_float2(sa[0], sb[0]);
}

__device__ __forceinline__ void split2(float a, float b, __nv_bfloat162& h2, __nv_bfloat162& l2) {
    __nv_bfloat16 ha = __float2bfloat16(a), hb = __float2bfloat16(b);
    float la = a - __bfloat162float(ha);
    float lb = b - __bfloat162float(hb);
    h2 = __halves2bfloat162(ha, hb);
    l2 = __halves2bfloat162(__float2bfloat16(la), __float2bfloat16(lb));
}

__global__ void __launch_bounds__(256) ln_silu_split_kernel(
    const float* __restrict__ x,
    const float* __restrict__ gamma,
    const float* __restrict__ beta,
    __nv_bfloat16* __restrict__ hi,
    __nv_bfloat16* __restrict__ lo)
{
    const size_t row = blockIdx.x;
    const int tid = threadIdx.x;
    const float4* xr = (const float4*)(x + row * (size_t)CH);

    float4 v0 = xr[tid];
    float4 v1 = xr[tid + 256];

    float s  = v0.x + v0.y + v0.z + v0.w + v1.x + v1.y + v1.z + v1.w;
    float sq = v0.x*v0.x + v0.y*v0.y + v0.z*v0.z + v0.w*v0.w
             + v1.x*v1.x + v1.y*v1.y + v1.z*v1.z + v1.w*v1.w;

    float2 r = block_reduce_sum2(s, sq);
    const float inv_n = 1.0f / (float)CH;
    float mu  = r.x * inv_n;
    float var = r.y * inv_n - mu * mu;
    float inv = rsqrtf(var + 1e-6f);

    const float4* gr = (const float4*)gamma;
    const float4* br = (const float4*)beta;
    float4 g0 = gr[tid], g1v = gr[tid + 256];
    float4 b0 = br[tid], b1v = br[tid + 256];

    float4 o0, o1;
    #define LNS(xx, gg, bb, oo) { float y = (xx - mu) * inv * gg + bb; oo = y * (1.0f / (1.0f + __expf(-y))); }
    LNS(v0.x, g0.x,  b0.x,  o0.x); LNS(v0.y, g0.y,  b0.y,  o0.y);
    LNS(v0.z, g0.z,  b0.z,  o0.z); LNS(v0.w, g0.w,  b0.w,  o0.w);
    LNS(v1.x, g1v.x, b1v.x, o1.x); LNS(v1.y, g1v.y, b1v.y, o1.y);
    LNS(v1.z, g1v.z, b1v.z, o1.z); LNS(v1.w, g1v.w, b1v.w, o1.w);
    #undef LNS

    __nv_bfloat162* oh = (__nv_bfloat162*)(hi + row * (size_t)CH);
    __nv_bfloat162* ol = (__nv_bfloat162*)(lo + row * (size_t)CH);
    __nv_bfloat162 H, L;
    split2(o0.x, o0.y, H, L); oh[2*tid]           = H; ol[2*tid]           = L;
    split2(o0.z, o0.w, H, L); oh[2*tid + 1]       = H; ol[2*tid + 1]       = L;
    split2(o1.x, o1.y, H, L); oh[512 + 2*tid]     = H; ol[512 + 2*tid]     = L;
    split2(o1.z, o1.w, H, L); oh[512 + 2*tid + 1] = H; ol[512 + 2*tid + 1] = L;
}

// ======================= weight transpose + bf16 split =======================
// in: w[k][n] fp32; out: wt[n][k] bf16 hi/lo (K contiguous)
__global__ void __launch_bounds__(256) wsplit_kernel(
    const float* __restrict__ w,
    __nv_bfloat16* __restrict__ hi,
    __nv_bfloat16* __restrict__ lo)
{
    __shared__ float t[32][33];
    const int k0 = blockIdx.y * 32, n0 = blockIdx.x * 32;
    for (int i = threadIdx.y; i < 32; i += 8)
        t[i][threadIdx.x] = w[(size_t)(k0 + i) * CH + n0 + threadIdx.x];
    __syncthreads();
    for (int i = threadIdx.y; i < 32; i += 8) {
        float v = t[threadIdx.x][i];
        size_t o = (size_t)(n0 + i) * CH + k0 + threadIdx.x;
        __nv_bfloat16 h = __float2bfloat16(v);
        hi[o] = h;
        lo[o] = __float2bfloat16(v - __bfloat162float(h));
    }
}

// ======================= HMMA 3x-bf16 GEMM =======================
// out[m, n] = sum_k A[m,k] * Wt[n,k]  (+bias[n]) (+resid[m,n])
template <bool RESID>
__global__ void __launch_bounds__(256, 1) hgemm3_kernel(
    const __nv_bfloat16* __restrict__ Ahi,
    const __nv_bfloat16* __restrict__ Alo,
    const __nv_bfloat16* __restrict__ Whi,
    const __nv_bfloat16* __restrict__ Wlo,
    const float* __restrict__ bias,
    const float* __restrict__ resid,
    float* __restrict__ out)
{
    extern __shared__ char smem_raw[];
    const uint32_t sbase = smem_u32(smem_raw);

    const int tid  = threadIdx.x;
    const int lane = tid & 31, wid = tid >> 5;
    const int warp_m = wid & 3;        // 0..3  (rows: warp_m*32)
    const int warp_n = wid >> 2;       // 0..1  (cols: warp_n*64)
    const int m0 = blockIdx.y * BM;
    const int n0 = blockIdx.x * BN;

    // cp.async mapping: thread handles kchunk lkc (16B) of rows lrow + {0,32,64,96}
    const int lrow = tid >> 3;         // 0..31
    const int lkc  = tid & 7;          // 0..7

    float acc[2][8][4];
    #pragma unroll
    for (int mt = 0; mt < 2; mt++)
        #pragma unroll
        for (int nt = 0; nt < 8; nt++)
            #pragma unroll
            for (int i = 0; i < 4; i++) acc[mt][nt][i] = 0.0f;

    auto load_stage = [&](int c) {
        const uint32_t st = sbase + (uint32_t)(c & 1) * STAGE_BYTES;
        const int k = c * BK + lkc * 8;
        #pragma unroll
        for (int i = 0; i < 4; i++) {
            const int row = lrow + i * 32;
            const uint32_t so = swz(row, lkc);
            const size_t ga = (size_t)(m0 + row) * CH + k;
            const size_t gw = (size_t)(n0 + row) * CH + k;
            cp16(st + OFF_AHI + so, Ahi + ga);
            cp16(st + OFF_ALO + so, Alo + ga);
            cp16(st + OFF_WHI + so, Whi + gw);
            cp16(st + OFF_WLO + so, Wlo + gw);
        }
        CP_COMMIT();
    };

    auto compute_stage = [&](int s) {
        const uint32_t st = sbase + (uint32_t)s * STAGE_BYTES;
        #pragma unroll
        for (int ks = 0; ks < BK / 16; ks++) {
            // --- A fragments (hi & lo), 2 m-tiles ---
            uint32_t ahi[2][4], alo[2][4];
            {
                const int r = warp_m * 32 + (lane & 15);
                const int kc = ks * 2 + (lane >> 4);
                #pragma unroll
                for (int mt = 0; mt < 2; mt++) {
                    const uint32_t o = swz(r + mt * 16, kc);
                    LDSM4(ahi[mt], st + OFF_AHI + o);
                    LDSM4(alo[mt], st + OFF_ALO + o);
                }
            }
            // --- B fragments (hi & lo), 8 n-tiles via 4 x4-ldmatrix ---
            uint32_t bhi[8][2], blo[8][2];
            {
                const int rb = warp_n * 64 + ((lane >> 4) & 1) * 8 + (lane & 7);
                const int kc = ks * 2 + ((lane >> 3) & 1);
                #pragma unroll
                for (int p = 0; p < 4; p++) {
                    const uint32_t o = swz(rb + p * 16, kc);
                    uint32_t r4[4];
                    LDSM4(r4, st + OFF_WHI + o);
                    bhi[2*p][0] = r4[0]; bhi[2*p][1] = r4[1];
                    bhi[2*p+1][0] = r4[2]; bhi[2*p+1][1] = r4[3];
                    LDSM4(r4, st + OFF_WLO + o);
                    blo[2*p][0] = r4[0]; blo[2*p][1] = r4[1];
                    blo[2*p+1][0] = r4[2]; blo[2*p+1][1] = r4[3];
                }
            }
            #pragma unroll
            for (int mt = 0; mt < 2; mt++)
                #pragma unroll
                for (int nt = 0; nt < 8; nt++) {
                    MMA16816(acc[mt][nt], ahi[mt], bhi[nt]);
                    MMA16816(acc[mt][nt], ahi[mt], blo[nt]);
                    MMA16816(acc[mt][nt], alo[mt], bhi[nt]);
                }
        }
    };

    load_stage(0);
    #pragma unroll 1
    for (int c = 0; c < CHUNKS; c++) {
        if (c + 1 < CHUNKS) {
            load_stage(c + 1);
            CP_WAIT1();
        } else {
            CP_WAIT0();
        }
        __syncthreads();
        compute_stage(c & 1);
        __syncthreads();
    }

    // ---- epilogue ----
    #pragma unroll
    for (int mt = 0; mt < 2; mt++) {
        const int r0 = m0 + warp_m * 32 + mt * 16 + (lane >> 2);
        #pragma unroll
        for (int nt = 0; nt < 8; nt++) {
            const int col = n0 + warp_n * 64 + nt * 8 + (lane & 3) * 2;
            const float bx = __ldg(&bias[col]);
            const float by = __ldg(&bias[col + 1]);
            float2 v0 = make_float2(acc[mt][nt][0] + bx, acc[mt][nt][1] + by);
            float2 v1 = make_float2(acc[mt][nt][2] + bx, acc[mt][nt][3] + by);
            if constexpr (RESID) {
                float2 ra = *(const float2*)(resid + (size_t)r0 * CH + col);
                float2 rb = *(const float2*)(resid + (size_t)(r0 + 8) * CH + col);
                v0.x += ra.x; v0.y += ra.y;
                v1.x += rb.x; v1.y += rb.y;
            }
            *(float2*)(out + (size_t)r0 * CH + col)       = v0;
            *(float2*)(out + (size_t)(r0 + 8) * CH + col) = v1;
        }
    }
}

// ======================= host =======================
extern "C" void kernel_launch(void* const* d_in, const int* in_sizes, int n_in,
                              void* d_out, int out_size)
{
    const float* x   = (const float*)d_in[0];
    const float* w1  = (const float*)d_in[1];
    const float* b1  = (const float*)d_in[2];
    const float* w2  = (const float*)d_in[3];
    const float* b2  = (const float*)d_in[4];
    const float* g1  = (const float*)d_in[5];
    const float* be1 = (const float*)d_in[6];
    const float* g2  = (const float*)d_in[7];
    const float* be2 = (const float*)d_in[8];
    float* out = (float*)d_out;

    void* p;
    cudaGetSymbolAddress(&p, g_act_hi); __nv_bfloat16* act_hi = (__nv_bfloat16*)p;
    cudaGetSymbolAddress(&p, g_act_lo); __nv_bfloat16* act_lo = (__nv_bfloat16*)p;
    cudaGetSymbolAddress(&p, g_h1);     float* h1 = (float*)p;
    cudaGetSymbolAddress(&p, g_w1_hi);  __nv_bfloat16* w1hi = (__nv_bfloat16*)p;
    cudaGetSymbolAddress(&p, g_w1_lo);  __nv_bfloat16* w1lo = (__nv_bfloat16*)p;
    cudaGetSymbolAddress(&p, g_w2_hi);  __nv_bfloat16* w2hi = (__nv_bfloat16*)p;
    cudaGetSymbolAddress(&p, g_w2_lo);  __nv_bfloat16* w2lo = (__nv_bfloat16*)p;

    cudaFuncSetAttribute(hgemm3_kernel<false>, cudaFuncAttributeMaxDynamicSharedMemorySize, SMEM_TOTAL);
    cudaFuncSetAttribute(hgemm3_kernel<true>,  cudaFuncAttributeMaxDynamicSharedMemorySize, SMEM_TOTAL);

    dim3 wgrid(CH / 32, CH / 32);
    dim3 wblk(32, 8);
    dim3 ggrid(CH / BN, ROWS / BM);   // (16, 256)

    wsplit_kernel<<<wgrid, wblk>>>(w1, w1hi, w1lo);
    wsplit_kernel<<<wgrid, wblk>>>(w2, w2hi, w2lo);
    ln_silu_split_kernel<<<ROWS, 256>>>(x, g1, be1, act_hi, act_lo);
    hgemm3_kernel<false><<<ggrid, 256, SMEM_TOTAL>>>(act_hi, act_lo, w1hi, w1lo, b1, nullptr, h1);
    ln_silu_split_kernel<<<ROWS, 256>>>(h1, g2, be2, act_hi, act_lo);
    hgemm3_kernel<true><<<ggrid, 256, SMEM_TOTAL>>>(act_hi, act_lo, w2hi, w2lo, b2, x, out);
}

// round 4
// speedup vs baseline: 7.1229x; 2.2360x over previous
#include <cuda_runtime.h>
#include <cuda_fp16.h>
#include <stdint.h>
#include <math.h>

#define ROWS   (8 * 4096)     // 32768
#define CH     2048
#define BM     128
#define BN     128
#define BK     64
#define CHUNKS (CH / BK)      // 32
#define NSTAGE 4

// per stage: A [128][64] half (16KB) + W [128][64] half (16KB)
#define MAT_BYTES   (128 * 64 * 2)
#define OFF_A       0
#define OFF_W       (MAT_BYTES)
#define STAGE_BYTES (2 * MAT_BYTES)          // 32KB
#define SMEM_TOTAL  (NSTAGE * STAGE_BYTES)   // 128KB

// ---- scratch (__device__ globals; allocation-free rule) ----
__device__ __half g_act[(size_t)ROWS * CH];
__device__ float  g_h1 [(size_t)ROWS * CH];
__device__ __half g_w1t[(size_t)CH * CH];
__device__ __half g_w2t[(size_t)CH * CH];

// ======================= PTX helpers =======================
__device__ __forceinline__ uint32_t smem_u32(const void* p) {
    uint32_t a;
    asm("{ .reg .u64 t; cvta.to.shared.u64 t, %1; cvt.u32.u64 %0, t; }" : "=r"(a) : "l"(p));
    return a;
}

__device__ __forceinline__ void cp16(uint32_t s, const void* g) {
    asm volatile("cp.async.cg.shared.global [%0], [%1], 16;" :: "r"(s), "l"(g));
}

#define CP_COMMIT()   asm volatile("cp.async.commit_group;" ::: "memory")
#define CP_WAIT(n)    asm volatile("cp.async.wait_group %0;" :: "n"(n) : "memory")

#define LDSM4(r, addr) \
    asm volatile("ldmatrix.sync.aligned.m8n8.x4.shared.b16 {%0,%1,%2,%3}, [%4];" \
        : "=r"((r)[0]), "=r"((r)[1]), "=r"((r)[2]), "=r"((r)[3]) : "r"(addr))

#define MMA16816(c, a, b) \
    asm volatile("mma.sync.aligned.m16n8k16.row.col.f32.f16.f16.f32 " \
        "{%0,%1,%2,%3}, {%4,%5,%6,%7}, {%8,%9}, {%0,%1,%2,%3};" \
        : "+f"((c)[0]), "+f"((c)[1]), "+f"((c)[2]), "+f"((c)[3]) \
        : "r"((a)[0]), "r"((a)[1]), "r"((a)[2]), "r"((a)[3]), "r"((b)[0]), "r"((b)[1]))

// swizzled smem byte offset for (row, 16B-chunk kc) in a [128][64]half matrix
__device__ __forceinline__ uint32_t swz(int row, int kc) {
    return (uint32_t)(row * 128 + ((kc ^ (row & 7)) << 4));
}

// ======================= LN + SiLU -> fp16 =======================
__inline__ __device__ float2 block_reduce_sum2(float a, float b) {
    __shared__ float sa[8], sb[8];
    int lane = threadIdx.x & 31, w = threadIdx.x >> 5;
    #pragma unroll
    for (int off = 16; off > 0; off >>= 1) {
        a += __shfl_down_sync(0xffffffffu, a, off);
        b += __shfl_down_sync(0xffffffffu, b, off);
    }
    if (lane == 0) { sa[w] = a; sb[w] = b; }
    __syncthreads();
    if (w == 0) {
        a = (lane < 8) ? sa[lane] : 0.0f;
        b = (lane < 8) ? sb[lane] : 0.0f;
        #pragma unroll
        for (int off = 4; off > 0; off >>= 1) {
            a += __shfl_down_sync(0xffffffffu, a, off);
            b += __shfl_down_sync(0xffffffffu, b, off);
        }
        if (lane == 0) { sa[0] = a; sb[0] = b; }
    }
    __syncthreads();
    return make_float2(sa[0], sb[0]);
}

__global__ void __launch_bounds__(256) ln_silu_h_kernel(
    const float* __restrict__ x,
    const float* __restrict__ gamma,
    const float* __restrict__ beta,
    __half* __restrict__ o)
{
    const size_t row = blockIdx.x;
    const int tid = threadIdx.x;
    const float4* xr = (const float4*)(x + row * (size_t)CH);

    float4 v0 = xr[tid];
    float4 v1 = xr[tid + 256];

    float s  = v0.x + v0.y + v0.z + v0.w + v1.x + v1.y + v1.z + v1.w;
    float sq = v0.x*v0.x + v0.y*v0.y + v0.z*v0.z + v0.w*v0.w
             + v1.x*v1.x + v1.y*v1.y + v1.z*v1.z + v1.w*v1.w;

    float2 r = block_reduce_sum2(s, sq);
    const float inv_n = 1.0f / (float)CH;
    float mu  = r.x * inv_n;
    float var = r.y * inv_n - mu * mu;
    float inv = rsqrtf(var + 1e-6f);

    const float4* gr = (const float4*)gamma;
    const float4* br = (const float4*)beta;
    float4 g0 = gr[tid], g1v = gr[tid + 256];
    float4 b0 = br[tid], b1v = br[tid + 256];

    float4 o0, o1;
    #define LNS(xx, gg, bb, oo) { float y = (xx - mu) * inv * gg + bb; oo = y * (1.0f / (1.0f + __expf(-y))); }
    LNS(v0.x, g0.x,  b0.x,  o0.x); LNS(v0.y, g0.y,  b0.y,  o0.y);
    LNS(v0.z, g0.z,  b0.z,  o0.z); LNS(v0.w, g0.w,  b0.w,  o0.w);
    LNS(v1.x, g1v.x, b1v.x, o1.x); LNS(v1.y, g1v.y, b1v.y, o1.y);
    LNS(v1.z, g1v.z, b1v.z, o1.z); LNS(v1.w, g1v.w, b1v.w, o1.w);
    #undef LNS

    __half2* oh = (__half2*)(o + row * (size_t)CH);
    oh[2*tid]           = __float22half2_rn(make_float2(o0.x, o0.y));
    oh[2*tid + 1]       = __float22half2_rn(make_float2(o0.z, o0.w));
    oh[512 + 2*tid]     = __float22half2_rn(make_float2(o1.x, o1.y));
    oh[512 + 2*tid + 1] = __float22half2_rn(make_float2(o1.z, o1.w));
}

// ======================= weight transpose -> fp16 =======================
// in: w[k][n] fp32; out: wt[n][k] fp16 (K contiguous)
__global__ void __launch_bounds__(256) wtrans_h_kernel(
    const float* __restrict__ w,
    __half* __restrict__ wt)
{
    __shared__ float t[32][33];
    const int k0 = blockIdx.y * 32, n0 = blockIdx.x * 32;
    for (int i = threadIdx.y; i < 32; i += 8)
        t[i][threadIdx.x] = w[(size_t)(k0 + i) * CH + n0 + threadIdx.x];
    __syncthreads();
    for (int i = threadIdx.y; i < 32; i += 8)
        wt[(size_t)(n0 + i) * CH + k0 + threadIdx.x] = __float2half_rn(t[threadIdx.x][i]);
}

// ======================= fp16 HMMA GEMM =======================
// out[m, n] = sum_k A[m,k] * Wt[n,k]  (+bias[n]) (+resid[m,n])
template <bool RESID>
__global__ void __launch_bounds__(256, 1) hgemm_kernel(
    const __half* __restrict__ A,
    const __half* __restrict__ W,
    const float* __restrict__ bias,
    const float* __restrict__ resid,
    float* __restrict__ out)
{
    extern __shared__ char smem_raw[];
    const uint32_t sbase = smem_u32(smem_raw);

    const int tid  = threadIdx.x;
    const int lane = tid & 31, wid = tid >> 5;
    const int warp_m = wid & 3;        // rows: warp_m*32
    const int warp_n = wid >> 2;       // cols: warp_n*64
    const int m0 = blockIdx.y * BM;
    const int n0 = blockIdx.x * BN;

    const int lrow = tid >> 3;         // 0..31
    const int lkc  = tid & 7;          // 0..7

    float acc[2][8][4];
    #pragma unroll
    for (int mt = 0; mt < 2; mt++)
        #pragma unroll
        for (int nt = 0; nt < 8; nt++)
            #pragma unroll
            for (int i = 0; i < 4; i++) acc[mt][nt][i] = 0.0f;

    auto load_stage = [&](int c) {
        const uint32_t st = sbase + (uint32_t)(c % NSTAGE) * STAGE_BYTES;
        const int k = c * BK + lkc * 8;
        #pragma unroll
        for (int i = 0; i < 4; i++) {
            const int row = lrow + i * 32;
            const uint32_t so = swz(row, lkc);
            cp16(st + OFF_A + so, A + (size_t)(m0 + row) * CH + k);
            cp16(st + OFF_W + so, W + (size_t)(n0 + row) * CH + k);
        }
        CP_COMMIT();
    };

    auto compute_stage = [&](int c) {
        const uint32_t st = sbase + (uint32_t)(c % NSTAGE) * STAGE_BYTES;
        #pragma unroll
        for (int ks = 0; ks < BK / 16; ks++) {
            uint32_t af[2][4];
            {
                const int r = warp_m * 32 + (lane & 15);
                const int kc = ks * 2 + (lane >> 4);
                #pragma unroll
                for (int mt = 0; mt < 2; mt++)
                    LDSM4(af[mt], st + OFF_A + swz(r + mt * 16, kc));
            }
            uint32_t bf[8][2];
            {
                const int rb = warp_n * 64 + ((lane >> 4) & 1) * 8 + (lane & 7);
                const int kc = ks * 2 + ((lane >> 3) & 1);
                #pragma unroll
                for (int p = 0; p < 4; p++) {
                    uint32_t r4[4];
                    LDSM4(r4, st + OFF_W + swz(rb + p * 16, kc));
                    bf[2*p][0]   = r4[0]; bf[2*p][1]   = r4[1];
                    bf[2*p+1][0] = r4[2]; bf[2*p+1][1] = r4[3];
                }
            }
            #pragma unroll
            for (int mt = 0; mt < 2; mt++)
                #pragma unroll
                for (int nt = 0; nt < 8; nt++)
                    MMA16816(acc[mt][nt], af[mt], bf[nt]);
        }
    };

    load_stage(0);
    load_stage(1);
    load_stage(2);
    #pragma unroll 1
    for (int c = 0; c < CHUNKS; c++) {
        CP_WAIT(2);              // stage c complete (≤2 newer groups outstanding)
        __syncthreads();
        compute_stage(c);
        if (c + 3 < CHUNKS) load_stage(c + 3);   // overwrites buffer of stage c-1 (done by sync)
    }

    // ---- epilogue ----
    #pragma unroll
    for (int mt = 0; mt < 2; mt++) {
        const int r0 = m0 + warp_m * 32 + mt * 16 + (lane >> 2);
        #pragma unroll
        for (int nt = 0; nt < 8; nt++) {
            const int col = n0 + warp_n * 64 + nt * 8 + (lane & 3) * 2;
            const float bx = __ldg(&bias[col]);
            const float by = __ldg(&bias[col + 1]);
            float2 v0 = make_float2(acc[mt][nt][0] + bx, acc[mt][nt][1] + by);
            float2 v1 = make_float2(acc[mt][nt][2] + bx, acc[mt][nt][3] + by);
            if constexpr (RESID) {
                float2 ra = *(const float2*)(resid + (size_t)r0 * CH + col);
                float2 rb = *(const float2*)(resid + (size_t)(r0 + 8) * CH + col);
                v0.x += ra.x; v0.y += ra.y;
                v1.x += rb.x; v1.y += rb.y;
            }
            *(float2*)(out + (size_t)r0 * CH + col)       = v0;
            *(float2*)(out + (size_t)(r0 + 8) * CH + col) = v1;
        }
    }
}

// ======================= host =======================
extern "C" void kernel_launch(void* const* d_in, const int* in_sizes, int n_in,
                              void* d_out, int out_size)
{
    const float* x   = (const float*)d_in[0];
    const float* w1  = (const float*)d_in[1];
    const float* b1  = (const float*)d_in[2];
    const float* w2  = (const float*)d_in[3];
    const float* b2  = (const float*)d_in[4];
    const float* g1  = (const float*)d_in[5];
    const float* be1 = (const float*)d_in[6];
    const float* g2  = (const float*)d_in[7];
    const float* be2 = (const float*)d_in[8];
    float* out = (float*)d_out;

    void* p;
    cudaGetSymbolAddress(&p, g_act); __half* act = (__half*)p;
    cudaGetSymbolAddress(&p, g_h1);  float* h1 = (float*)p;
    cudaGetSymbolAddress(&p, g_w1t); __half* w1t = (__half*)p;
    cudaGetSymbolAddress(&p, g_w2t); __half* w2t = (__half*)p;

    cudaFuncSetAttribute(hgemm_kernel<false>, cudaFuncAttributeMaxDynamicSharedMemorySize, SMEM_TOTAL);
    cudaFuncSetAttribute(hgemm_kernel<true>,  cudaFuncAttributeMaxDynamicSharedMemorySize, SMEM_TOTAL);

    dim3 wgrid(CH / 32, CH / 32);
    dim3 wblk(32, 8);
    dim3 ggrid(CH / BN, ROWS / BM);   // (16, 256)

    wtrans_h_kernel<<<wgrid, wblk>>>(w1, w1t);
    wtrans_h_kernel<<<wgrid, wblk>>>(w2, w2t);
    ln_silu_h_kernel<<<ROWS, 256>>>(x, g1, be1, act);
    hgemm_kernel<false><<<ggrid, 256, SMEM_TOTAL>>>(act, w1t, b1, nullptr, h1);
    ln_silu_h_kernel<<<ROWS, 256>>>(h1, g2, be2, act);
    hgemm_kernel<true><<<ggrid, 256, SMEM_TOTAL>>>(act, w2t, b2, x, out);
}

// round 5
// speedup vs baseline: 7.9870x; 1.1213x over previous
#include <cuda_runtime.h>
#include <cuda_fp16.h>
#include <stdint.h>
#include <math.h>

#define ROWS   (8 * 4096)     // 32768
#define CH     2048
#define BM     256
#define BN     128
#define BK     64
#define CHUNKS (CH / BK)      // 32
#define NSTAGE 4

// per stage: A [256][64] half (32KB) + W [128][64] half (16KB)
#define A_BYTES     (256 * 64 * 2)
#define W_BYTES     (128 * 64 * 2)
#define OFF_A       0
#define OFF_W       (A_BYTES)
#define STAGE_BYTES (A_BYTES + W_BYTES)      // 48KB
#define SMEM_TOTAL  (NSTAGE * STAGE_BYTES)   // 192KB

// ---- scratch (__device__ globals; allocation-free rule) ----
__device__ __half g_act[(size_t)ROWS * CH];
__device__ float  g_h1 [(size_t)ROWS * CH];
__device__ __half g_w1t[(size_t)CH * CH];
__device__ __half g_w2t[(size_t)CH * CH];

// ======================= PTX helpers =======================
__device__ __forceinline__ uint32_t smem_u32(const void* p) {
    uint32_t a;
    asm("{ .reg .u64 t; cvta.to.shared.u64 t, %1; cvt.u32.u64 %0, t; }" : "=r"(a) : "l"(p));
    return a;
}

__device__ __forceinline__ void cp16(uint32_t s, const void* g) {
    asm volatile("cp.async.cg.shared.global [%0], [%1], 16;" :: "r"(s), "l"(g));
}

#define CP_COMMIT()   asm volatile("cp.async.commit_group;" ::: "memory")
#define CP_WAIT(n)    asm volatile("cp.async.wait_group %0;" :: "n"(n) : "memory")

#define LDSM4(r, addr) \
    asm volatile("ldmatrix.sync.aligned.m8n8.x4.shared.b16 {%0,%1,%2,%3}, [%4];" \
        : "=r"((r)[0]), "=r"((r)[1]), "=r"((r)[2]), "=r"((r)[3]) : "r"(addr))

#define MMA16816(c, a, b) \
    asm volatile("mma.sync.aligned.m16n8k16.row.col.f32.f16.f16.f32 " \
        "{%0,%1,%2,%3}, {%4,%5,%6,%7}, {%8,%9}, {%0,%1,%2,%3};" \
        : "+f"((c)[0]), "+f"((c)[1]), "+f"((c)[2]), "+f"((c)[3]) \
        : "r"((a)[0]), "r"((a)[1]), "r"((a)[2]), "r"((a)[3]), "r"((b)[0]), "r"((b)[1]))

// swizzled smem byte offset for (row, 16B-chunk kc) in a [rows][64]half matrix
__device__ __forceinline__ uint32_t swz(int row, int kc) {
    return (uint32_t)(row * 128 + ((kc ^ (row & 7)) << 4));
}

// ======================= LN + SiLU -> fp16 =======================
__inline__ __device__ float2 block_reduce_sum2(float a, float b) {
    __shared__ float sa[8], sb[8];
    int lane = threadIdx.x & 31, w = threadIdx.x >> 5;
    #pragma unroll
    for (int off = 16; off > 0; off >>= 1) {
        a += __shfl_down_sync(0xffffffffu, a, off);
        b += __shfl_down_sync(0xffffffffu, b, off);
    }
    if (lane == 0) { sa[w] = a; sb[w] = b; }
    __syncthreads();
    if (w == 0) {
        a = (lane < 8) ? sa[lane] : 0.0f;
        b = (lane < 8) ? sb[lane] : 0.0f;
        #pragma unroll
        for (int off = 4; off > 0; off >>= 1) {
            a += __shfl_down_sync(0xffffffffu, a, off);
            b += __shfl_down_sync(0xffffffffu, b, off);
        }
        if (lane == 0) { sa[0] = a; sb[0] = b; }
    }
    __syncthreads();
    return make_float2(sa[0], sb[0]);
}

__global__ void __launch_bounds__(256) ln_silu_h_kernel(
    const float* __restrict__ x,
    const float* __restrict__ gamma,
    const float* __restrict__ beta,
    __half* __restrict__ o)
{
    const size_t row = blockIdx.x;
    const int tid = threadIdx.x;
    const float4* xr = (const float4*)(x + row * (size_t)CH);

    float4 v0 = xr[tid];
    float4 v1 = xr[tid + 256];

    float s  = v0.x + v0.y + v0.z + v0.w + v1.x + v1.y + v1.z + v1.w;
    float sq = v0.x*v0.x + v0.y*v0.y + v0.z*v0.z + v0.w*v0.w
             + v1.x*v1.x + v1.y*v1.y + v1.z*v1.z + v1.w*v1.w;

    float2 r = block_reduce_sum2(s, sq);
    const float inv_n = 1.0f / (float)CH;
    float mu  = r.x * inv_n;
    float var = r.y * inv_n - mu * mu;
    float inv = rsqrtf(var + 1e-6f);

    const float4* gr = (const float4*)gamma;
    const float4* br = (const float4*)beta;
    float4 g0 = gr[tid], g1v = gr[tid + 256];
    float4 b0 = br[tid], b1v = br[tid + 256];

    float4 o0, o1;
    #define LNS(xx, gg, bb, oo) { float y = (xx - mu) * inv * gg + bb; oo = y * (1.0f / (1.0f + __expf(-y))); }
    LNS(v0.x, g0.x,  b0.x,  o0.x); LNS(v0.y, g0.y,  b0.y,  o0.y);
    LNS(v0.z, g0.z,  b0.z,  o0.z); LNS(v0.w, g0.w,  b0.w,  o0.w);
    LNS(v1.x, g1v.x, b1v.x, o1.x); LNS(v1.y, g1v.y, b1v.y, o1.y);
    LNS(v1.z, g1v.z, b1v.z, o1.z); LNS(v1.w, g1v.w, b1v.w, o1.w);
    #undef LNS

    __half2* oh = (__half2*)(o + row * (size_t)CH);
    oh[2*tid]           = __float22half2_rn(make_float2(o0.x, o0.y));
    oh[2*tid + 1]       = __float22half2_rn(make_float2(o0.z, o0.w));
    oh[512 + 2*tid]     = __float22half2_rn(make_float2(o1.x, o1.y));
    oh[512 + 2*tid + 1] = __float22half2_rn(make_float2(o1.z, o1.w));
}

// ======================= weight transpose -> fp16 =======================
__global__ void __launch_bounds__(256) wtrans_h_kernel(
    const float* __restrict__ w,
    __half* __restrict__ wt)
{
    __shared__ float t[32][33];
    const int k0 = blockIdx.y * 32, n0 = blockIdx.x * 32;
    for (int i = threadIdx.y; i < 32; i += 8)
        t[i][threadIdx.x] = w[(size_t)(k0 + i) * CH + n0 + threadIdx.x];
    __syncthreads();
    for (int i = threadIdx.y; i < 32; i += 8)
        wt[(size_t)(n0 + i) * CH + k0 + threadIdx.x] = __float2half_rn(t[threadIdx.x][i]);
}

// ======================= fp16 HMMA GEMM (64x64 warp tiles) =======================
// out[m, n] = sum_k A[m,k] * Wt[n,k]  (+bias[n]) (+resid[m,n])
template <bool RESID>
__global__ void __launch_bounds__(256, 1) hgemm_kernel(
    const __half* __restrict__ A,
    const __half* __restrict__ W,
    const float* __restrict__ bias,
    const float* __restrict__ resid,
    float* __restrict__ out)
{
    extern __shared__ char smem_raw[];
    const uint32_t sbase = smem_u32(smem_raw);

    const int tid  = threadIdx.x;
    const int lane = tid & 31, wid = tid >> 5;
    const int warp_m = wid & 3;        // rows: warp_m*64  (BM=256)
    const int warp_n = wid >> 2;       // cols: warp_n*64  (BN=128)
    const int m0 = blockIdx.y * BM;
    const int n0 = blockIdx.x * BN;

    const int lrow = tid >> 3;         // 0..31
    const int lkc  = tid & 7;          // 0..7

    float acc[4][8][4];
    #pragma unroll
    for (int mt = 0; mt < 4; mt++)
        #pragma unroll
        for (int nt = 0; nt < 8; nt++)
            #pragma unroll
            for (int i = 0; i < 4; i++) acc[mt][nt][i] = 0.0f;

    auto load_stage = [&](int c) {
        const uint32_t st = sbase + (uint32_t)(c % NSTAGE) * STAGE_BYTES;
        const int k = c * BK + lkc * 8;
        #pragma unroll
        for (int i = 0; i < 8; i++) {
            const int row = lrow + i * 32;
            cp16(st + OFF_A + swz(row, lkc), A + (size_t)(m0 + row) * CH + k);
        }
        #pragma unroll
        for (int i = 0; i < 4; i++) {
            const int row = lrow + i * 32;
            cp16(st + OFF_W + swz(row, lkc), W + (size_t)(n0 + row) * CH + k);
        }
        CP_COMMIT();
    };

    auto compute_stage = [&](int c) {
        const uint32_t st = sbase + (uint32_t)(c % NSTAGE) * STAGE_BYTES;
        #pragma unroll
        for (int ks = 0; ks < BK / 16; ks++) {
            uint32_t af[4][4];
            {
                const int r = warp_m * 64 + (lane & 15);
                const int kc = ks * 2 + (lane >> 4);
                #pragma unroll
                for (int mt = 0; mt < 4; mt++)
                    LDSM4(af[mt], st + OFF_A + swz(r + mt * 16, kc));
            }
            uint32_t bf[8][2];
            {
                const int rb = warp_n * 64 + ((lane >> 4) & 1) * 8 + (lane & 7);
                const int kc = ks * 2 + ((lane >> 3) & 1);
                #pragma unroll
                for (int p = 0; p < 4; p++) {
                    uint32_t r4[4];
                    LDSM4(r4, st + OFF_W + swz(rb + p * 16, kc));
                    bf[2*p][0]   = r4[0]; bf[2*p][1]   = r4[1];
                    bf[2*p+1][0] = r4[2]; bf[2*p+1][1] = r4[3];
                }
            }
            #pragma unroll
            for (int mt = 0; mt < 4; mt++)
                #pragma unroll
                for (int nt = 0; nt < 8; nt++)
                    MMA16816(acc[mt][nt], af[mt], bf[nt]);
        }
    };

    load_stage(0);
    load_stage(1);
    load_stage(2);
    #pragma unroll 1
    for (int c = 0; c < CHUNKS; c++) {
        CP_WAIT(2);
        __syncthreads();
        compute_stage(c);
        if (c + 3 < CHUNKS) load_stage(c + 3);
    }

    // ---- epilogue ----
    #pragma unroll
    for (int mt = 0; mt < 4; mt++) {
        const int r0 = m0 + warp_m * 64 + mt * 16 + (lane >> 2);
        #pragma unroll
        for (int nt = 0; nt < 8; nt++) {
            const int col = n0 + warp_n * 64 + nt * 8 + (lane & 3) * 2;
            const float bx = __ldg(&bias[col]);
            const float by = __ldg(&bias[col + 1]);
            float2 v0 = make_float2(acc[mt][nt][0] + bx, acc[mt][nt][1] + by);
            float2 v1 = make_float2(acc[mt][nt][2] + bx, acc[mt][nt][3] + by);
            if constexpr (RESID) {
                float2 ra = *(const float2*)(resid + (size_t)r0 * CH + col);
                float2 rb = *(const float2*)(resid + (size_t)(r0 + 8) * CH + col);
                v0.x += ra.x; v0.y += ra.y;
                v1.x += rb.x; v1.y += rb.y;
            }
            *(float2*)(out + (size_t)r0 * CH + col)       = v0;
            *(float2*)(out + (size_t)(r0 + 8) * CH + col) = v1;
        }
    }
}

// ======================= host =======================
extern "C" void kernel_launch(void* const* d_in, const int* in_sizes, int n_in,
                              void* d_out, int out_size)
{
    const float* x   = (const float*)d_in[0];
    const float* w1  = (const float*)d_in[1];
    const float* b1  = (const float*)d_in[2];
    const float* w2  = (const float*)d_in[3];
    const float* b2  = (const float*)d_in[4];
    const float* g1  = (const float*)d_in[5];
    const float* be1 = (const float*)d_in[6];
    const float* g2  = (const float*)d_in[7];
    const float* be2 = (const float*)d_in[8];
    float* out = (float*)d_out;

    void* p;
    cudaGetSymbolAddress(&p, g_act); __half* act = (__half*)p;
    cudaGetSymbolAddress(&p, g_h1);  float* h1 = (float*)p;
    cudaGetSymbolAddress(&p, g_w1t); __half* w1t = (__half*)p;
    cudaGetSymbolAddress(&p, g_w2t); __half* w2t = (__half*)p;

    cudaFuncSetAttribute(hgemm_kernel<false>, cudaFuncAttributeMaxDynamicSharedMemorySize, SMEM_TOTAL);
    cudaFuncSetAttribute(hgemm_kernel<true>,  cudaFuncAttributeMaxDynamicSharedMemorySize, SMEM_TOTAL);

    dim3 wgrid(CH / 32, CH / 32);
    dim3 wblk(32, 8);
    dim3 ggrid(CH / BN, ROWS / BM);   // (16, 128)

    wtrans_h_kernel<<<wgrid, wblk>>>(w1, w1t);
    wtrans_h_kernel<<<wgrid, wblk>>>(w2, w2t);
    ln_silu_h_kernel<<<ROWS, 256>>>(x, g1, be1, act);
    hgemm_kernel<false><<<ggrid, 256, SMEM_TOTAL>>>(act, w1t, b1, nullptr, h1);
    ln_silu_h_kernel<<<ROWS, 256>>>(h1, g2, be2, act);
    hgemm_kernel<true><<<ggrid, 256, SMEM_TOTAL>>>(act, w2t, b2, x, out);
}

// round 6
// speedup vs baseline: 8.1028x; 1.0145x over previous
#include <cuda_runtime.h>
#include <cuda_fp16.h>
#include <stdint.h>
#include <math.h>

#define ROWS   (8 * 4096)     // 32768
#define CH     2048
#define BM     256
#define BN     128
#define BK     64
#define CHUNKS (CH / BK)      // 32 per tile
#define NSTAGE 4
#define NT_N   (CH / BN)      // 16
#define NT_M   (ROWS / BM)    // 128
#define NTILES (NT_M * NT_N)  // 2048

// per stage: A [256][64] half (32KB) + W [128][64] half (16KB)
#define A_BYTES     (256 * 64 * 2)
#define W_BYTES     (128 * 64 * 2)
#define OFF_A       0
#define OFF_W       (A_BYTES)
#define STAGE_BYTES (A_BYTES + W_BYTES)      // 48KB
#define SMEM_TOTAL  (NSTAGE * STAGE_BYTES)   // 192KB

// ---- scratch (__device__ globals; allocation-free rule) ----
__device__ __half g_act[(size_t)ROWS * CH];
__device__ __half g_h1 [(size_t)ROWS * CH];
__device__ __half g_w1t[(size_t)CH * CH];
__device__ __half g_w2t[(size_t)CH * CH];

// ======================= PTX helpers =======================
__device__ __forceinline__ uint32_t smem_u32(const void* p) {
    uint32_t a;
    asm("{ .reg .u64 t; cvta.to.shared.u64 t, %1; cvt.u32.u64 %0, t; }" : "=r"(a) : "l"(p));
    return a;
}

__device__ __forceinline__ void cp16(uint32_t s, const void* g) {
    asm volatile("cp.async.cg.shared.global [%0], [%1], 16;" :: "r"(s), "l"(g));
}

#define CP_COMMIT()   asm volatile("cp.async.commit_group;" ::: "memory")
#define CP_WAIT(n)    asm volatile("cp.async.wait_group %0;" :: "n"(n) : "memory")

#define LDSM4(r, addr) \
    asm volatile("ldmatrix.sync.aligned.m8n8.x4.shared.b16 {%0,%1,%2,%3}, [%4];" \
        : "=r"((r)[0]), "=r"((r)[1]), "=r"((r)[2]), "=r"((r)[3]) : "r"(addr))

#define MMA16816(c, a, b) \
    asm volatile("mma.sync.aligned.m16n8k16.row.col.f32.f16.f16.f32 " \
        "{%0,%1,%2,%3}, {%4,%5,%6,%7}, {%8,%9}, {%0,%1,%2,%3};" \
        : "+f"((c)[0]), "+f"((c)[1]), "+f"((c)[2]), "+f"((c)[3]) \
        : "r"((a)[0]), "r"((a)[1]), "r"((a)[2]), "r"((a)[3]), "r"((b)[0]), "r"((b)[1]))

// swizzled smem byte offset for (row, 16B-chunk kc) in a [rows][64]half matrix
__device__ __forceinline__ uint32_t swz(int row, int kc) {
    return (uint32_t)(row * 128 + ((kc ^ (row & 7)) << 4));
}

// ======================= block reduction =======================
__inline__ __device__ float2 block_reduce_sum2(float a, float b) {
    __shared__ float sa[8], sb[8];
    int lane = threadIdx.x & 31, w = threadIdx.x >> 5;
    #pragma unroll
    for (int off = 16; off > 0; off >>= 1) {
        a += __shfl_down_sync(0xffffffffu, a, off);
        b += __shfl_down_sync(0xffffffffu, b, off);
    }
    if (lane == 0) { sa[w] = a; sb[w] = b; }
    __syncthreads();
    if (w == 0) {
        a = (lane < 8) ? sa[lane] : 0.0f;
        b = (lane < 8) ? sb[lane] : 0.0f;
        #pragma unroll
        for (int off = 4; off > 0; off >>= 1) {
            a += __shfl_down_sync(0xffffffffu, a, off);
            b += __shfl_down_sync(0xffffffffu, b, off);
        }
        if (lane == 0) { sa[0] = a; sb[0] = b; }
    }
    __syncthreads();
    return make_float2(sa[0], sb[0]);
}

// ======================= LN + SiLU (fp32 in) -> fp16 =======================
__global__ void __launch_bounds__(256) ln_silu_f32_kernel(
    const float* __restrict__ x,
    const float* __restrict__ gamma,
    const float* __restrict__ beta,
    __half* __restrict__ o)
{
    const size_t row = blockIdx.x;
    const int tid = threadIdx.x;
    const float4* xr = (const float4*)(x + row * (size_t)CH);

    float4 v0 = xr[2*tid];
    float4 v1 = xr[2*tid + 1];

    float s  = v0.x + v0.y + v0.z + v0.w + v1.x + v1.y + v1.z + v1.w;
    float sq = v0.x*v0.x + v0.y*v0.y + v0.z*v0.z + v0.w*v0.w
             + v1.x*v1.x + v1.y*v1.y + v1.z*v1.z + v1.w*v1.w;

    float2 r = block_reduce_sum2(s, sq);
    const float inv_n = 1.0f / (float)CH;
    float mu  = r.x * inv_n;
    float var = r.y * inv_n - mu * mu;
    float inv = rsqrtf(var + 1e-6f);

    const float4* gr = (const float4*)gamma;
    const float4* br = (const float4*)beta;
    float4 g0 = gr[2*tid], g1v = gr[2*tid + 1];
    float4 b0 = br[2*tid], b1v = br[2*tid + 1];

    float o8[8];
    #define LNS(xx, gg, bb, oo) { float y = (xx - mu) * inv * gg + bb; oo = y * (1.0f / (1.0f + __expf(-y))); }
    LNS(v0.x, g0.x,  b0.x,  o8[0]); LNS(v0.y, g0.y,  b0.y,  o8[1]);
    LNS(v0.z, g0.z,  b0.z,  o8[2]); LNS(v0.w, g0.w,  b0.w,  o8[3]);
    LNS(v1.x, g1v.x, b1v.x, o8[4]); LNS(v1.y, g1v.y, b1v.y, o8[5]);
    LNS(v1.z, g1v.z, b1v.z, o8[6]); LNS(v1.w, g1v.w, b1v.w, o8[7]);
    #undef LNS

    __half2 h4[4];
    #pragma unroll
    for (int i = 0; i < 4; i++) h4[i] = __float22half2_rn(make_float2(o8[2*i], o8[2*i+1]));
    *(uint4*)((__half2*)(o + row * (size_t)CH) + 4*tid) = *(uint4*)h4;
}

// ======================= LN + SiLU (fp16 in) -> fp16 =======================
__global__ void __launch_bounds__(256) ln_silu_f16_kernel(
    const __half* __restrict__ x,
    const float* __restrict__ gamma,
    const float* __restrict__ beta,
    __half* __restrict__ o)
{
    const size_t row = blockIdx.x;
    const int tid = threadIdx.x;

    uint4 raw = *(const uint4*)((const __half2*)(x + row * (size_t)CH) + 4*tid);
    __half2 h2[4];
    *(uint4*)h2 = raw;
    float v[8];
    #pragma unroll
    for (int i = 0; i < 4; i++) {
        float2 f = __half22float2(h2[i]);
        v[2*i] = f.x; v[2*i+1] = f.y;
    }

    float s = 0.f, sq = 0.f;
    #pragma unroll
    for (int i = 0; i < 8; i++) { s += v[i]; sq += v[i]*v[i]; }

    float2 r = block_reduce_sum2(s, sq);
    const float inv_n = 1.0f / (float)CH;
    float mu  = r.x * inv_n;
    float var = r.y * inv_n - mu * mu;
    float inv = rsqrtf(var + 1e-6f);

    const float4* gr = (const float4*)gamma;
    const float4* br = (const float4*)beta;
    float4 g0 = gr[2*tid], g1v = gr[2*tid + 1];
    float4 b0 = br[2*tid], b1v = br[2*tid + 1];
    float gg[8] = {g0.x, g0.y, g0.z, g0.w, g1v.x, g1v.y, g1v.z, g1v.w};
    float bb[8] = {b0.x, b0.y, b0.z, b0.w, b1v.x, b1v.y, b1v.z, b1v.w};

    float o8[8];
    #pragma unroll
    for (int i = 0; i < 8; i++) {
        float y = (v[i] - mu) * inv * gg[i] + bb[i];
        o8[i] = y * (1.0f / (1.0f + __expf(-y)));
    }

    __half2 h4[4];
    #pragma unroll
    for (int i = 0; i < 4; i++) h4[i] = __float22half2_rn(make_float2(o8[2*i], o8[2*i+1]));
    *(uint4*)((__half2*)(o + row * (size_t)CH) + 4*tid) = *(uint4*)h4;
}

// ======================= weight transpose -> fp16 =======================
__global__ void __launch_bounds__(256) wtrans_h_kernel(
    const float* __restrict__ w,
    __half* __restrict__ wt)
{
    __shared__ float t[32][33];
    const int k0 = blockIdx.y * 32, n0 = blockIdx.x * 32;
    for (int i = threadIdx.y; i < 32; i += 8)
        t[i][threadIdx.x] = w[(size_t)(k0 + i) * CH + n0 + threadIdx.x];
    __syncthreads();
    for (int i = threadIdx.y; i < 32; i += 8)
        wt[(size_t)(n0 + i) * CH + k0 + threadIdx.x] = __float2half_rn(t[threadIdx.x][i]);
}

// ======================= persistent fp16 HMMA GEMM (64x64 warp tiles) =======================
// out[m, n] = sum_k A[m,k] * Wt[n,k]  (+bias[n]) (+resid[m,n])
// OUTH=true: store fp16 (no resid). OUTH=false: store fp32 (optional resid).
template <bool RESID, bool OUTH>
__global__ void __launch_bounds__(256, 1) hgemm_kernel(
    const __half* __restrict__ A,
    const __half* __restrict__ W,
    const float* __restrict__ bias,
    const float* __restrict__ resid,
    float* __restrict__ outf,
    __half* __restrict__ outh)
{
    extern __shared__ char smem_raw[];
    const uint32_t sbase = smem_u32(smem_raw);

    const int tid  = threadIdx.x;
    const int lane = tid & 31, wid = tid >> 5;
    const int warp_m = wid & 3;        // rows: warp_m*64  (BM=256)
    const int warp_n = wid >> 2;       // cols: warp_n*64  (BN=128)

    const int bid = blockIdx.x;
    const int G   = gridDim.x;
    const int my_ntiles = (NTILES - bid + G - 1) / G;
    const int total_gc  = my_ntiles * CHUNKS;

    const int lrow = tid >> 3;         // 0..31
    const int lkc  = tid & 7;          // 0..7

    float acc[4][8][4];
    #pragma unroll
    for (int mt = 0; mt < 4; mt++)
        #pragma unroll
        for (int nt = 0; nt < 8; nt++)
            #pragma unroll
            for (int i = 0; i < 4; i++) acc[mt][nt][i] = 0.0f;

    auto load_stage = [&](int gc) {
        const int t  = bid + (gc >> 5) * G;
        const int m0 = (t >> 4) * BM;
        const int n0 = (t & 15) * BN;
        const int k  = (gc & 31) * BK + lkc * 8;
        const uint32_t st = sbase + (uint32_t)(gc % NSTAGE) * STAGE_BYTES;
        #pragma unroll
        for (int i = 0; i < 8; i++) {
            const int row = lrow + i * 32;
            cp16(st + OFF_A + swz(row, lkc), A + (size_t)(m0 + row) * CH + k);
        }
        #pragma unroll
        for (int i = 0; i < 4; i++) {
            const int row = lrow + i * 32;
            cp16(st + OFF_W + swz(row, lkc), W + (size_t)(n0 + row) * CH + k);
        }
        CP_COMMIT();
    };

    auto compute_stage = [&](int gc) {
        const uint32_t st = sbase + (uint32_t)(gc % NSTAGE) * STAGE_BYTES;
        #pragma unroll
        for (int ks = 0; ks < BK / 16; ks++) {
            uint32_t af[4][4];
            {
                const int r = warp_m * 64 + (lane & 15);
                const int kc = ks * 2 + (lane >> 4);
                #pragma unroll
                for (int mt = 0; mt < 4; mt++)
                    LDSM4(af[mt], st + OFF_A + swz(r + mt * 16, kc));
            }
            uint32_t bf[8][2];
            {
                const int rb = warp_n * 64 + ((lane >> 4) & 1) * 8 + (lane & 7);
                const int kc = ks * 2 + ((lane >> 3) & 1);
                #pragma unroll
                for (int p = 0; p < 4; p++) {
                    uint32_t r4[4];
                    LDSM4(r4, st + OFF_W + swz(rb + p * 16, kc));
                    bf[2*p][0]   = r4[0]; bf[2*p][1]   = r4[1];
                    bf[2*p+1][0] = r4[2]; bf[2*p+1][1] = r4[3];
                }
            }
            #pragma unroll
            for (int mt = 0; mt < 4; mt++)
                #pragma unroll
                for (int nt = 0; nt < 8; nt++)
                    MMA16816(acc[mt][nt], af[mt], bf[nt]);
        }
    };

    auto epilogue = [&](int t) {
        const int m0 = (t >> 4) * BM;
        const int n0 = (t & 15) * BN;
        #pragma unroll
        for (int mt = 0; mt < 4; mt++) {
            const int r0 = m0 + warp_m * 64 + mt * 16 + (lane >> 2);
            #pragma unroll
            for (int nt = 0; nt < 8; nt++) {
                const int col = n0 + warp_n * 64 + nt * 8 + (lane & 3) * 2;
                const float bx = __ldg(&bias[col]);
                const float by = __ldg(&bias[col + 1]);
                float2 v0 = make_float2(acc[mt][nt][0] + bx, acc[mt][nt][1] + by);
                float2 v1 = make_float2(acc[mt][nt][2] + bx, acc[mt][nt][3] + by);
                if constexpr (OUTH) {
                    *(__half2*)(outh + (size_t)r0 * CH + col)       = __float22half2_rn(v0);
                    *(__half2*)(outh + (size_t)(r0 + 8) * CH + col) = __float22half2_rn(v1);
                } else {
                    if constexpr (RESID) {
                        float2 ra = *(const float2*)(resid + (size_t)r0 * CH + col);
                        float2 rb = *(const float2*)(resid + (size_t)(r0 + 8) * CH + col);
                        v0.x += ra.x; v0.y += ra.y;
                        v1.x += rb.x; v1.y += rb.y;
                    }
                    *(float2*)(outf + (size_t)r0 * CH + col)       = v0;
                    *(float2*)(outf + (size_t)(r0 + 8) * CH + col) = v1;
                }
                acc[mt][nt][0] = 0.f; acc[mt][nt][1] = 0.f;
                acc[mt][nt][2] = 0.f; acc[mt][nt][3] = 0.f;
            }
        }
    };

    if (total_gc <= 0) return;
    load_stage(0);
    if (1 < total_gc) load_stage(1);
    if (2 < total_gc) load_stage(2);

    #pragma unroll 1
    for (int gc = 0; gc < total_gc; gc++) {
        CP_WAIT(2);
        __syncthreads();
        compute_stage(gc);
        if (gc + 3 < total_gc) load_stage(gc + 3);
        if ((gc & 31) == 31) epilogue(bid + (gc >> 5) * G);
    }
}

// ======================= host =======================
extern "C" void kernel_launch(void* const* d_in, const int* in_sizes, int n_in,
                              void* d_out, int out_size)
{
    const float* x   = (const float*)d_in[0];
    const float* w1  = (const float*)d_in[1];
    const float* b1  = (const float*)d_in[2];
    const float* w2  = (const float*)d_in[3];
    const float* b2  = (const float*)d_in[4];
    const float* g1  = (const float*)d_in[5];
    const float* be1 = (const float*)d_in[6];
    const float* g2  = (const float*)d_in[7];
    const float* be2 = (const float*)d_in[8];
    float* out = (float*)d_out;

    void* p;
    cudaGetSymbolAddress(&p, g_act); __half* act = (__half*)p;
    cudaGetSymbolAddress(&p, g_h1);  __half* h1 = (__half*)p;
    cudaGetSymbolAddress(&p, g_w1t); __half* w1t = (__half*)p;
    cudaGetSymbolAddress(&p, g_w2t); __half* w2t = (__half*)p;

    int nsm = 148;
    cudaDeviceGetAttribute(&nsm, cudaDevAttrMultiProcessorCount, 0);

    cudaFuncSetAttribute((const void*)hgemm_kernel<false, true>,
                         cudaFuncAttributeMaxDynamicSharedMemorySize, SMEM_TOTAL);
    cudaFuncSetAttribute((const void*)hgemm_kernel<true, false>,
                         cudaFuncAttributeMaxDynamicSharedMemorySize, SMEM_TOTAL);

    dim3 wgrid(CH / 32, CH / 32);
    dim3 wblk(32, 8);

    wtrans_h_kernel<<<wgrid, wblk>>>(w1, w1t);
    wtrans_h_kernel<<<wgrid, wblk>>>(w2, w2t);
    ln_silu_f32_kernel<<<ROWS, 256>>>(x, g1, be1, act);
    hgemm_kernel<false, true><<<nsm, 256, SMEM_TOTAL>>>(act, w1t, b1, nullptr, nullptr, h1);
    ln_silu_f16_kernel<<<ROWS, 256>>>(h1, g2, be2, act);
    hgemm_kernel<true, false><<<nsm, 256, SMEM_TOTAL>>>(act, w2t, b2, x, out, nullptr);
}